// round 2
// baseline (speedup 1.0000x reference)
#include <cuda_runtime.h>
#include <cstdint>

// ChamferDistance on GB300 — packed f32x2 FFMA inner loop.
// Inputs: xyz1 [B,N,3] f32, xyz2 [B,M,3] f32, B=8, N=M=8192.
// Output: dist1 [B*N] then dist2 [B*M].
//
// Per pair: d = sq2_j - 2*<q, r_j>, computed as
//   d = fma2(qz', pz2, fma2(qy', py2, fma2(qx', px2, sq2_2)))
// with q' = -2*q pre-folded, 2 query points packed per f32x2 op.
// min over j kept as scalar FMNMX (alu pipe, non-binding).

#define CD_THREADS 256
#define CD_P       4      // query points per thread (2 f32x2 packs)
#define CD_TILE    256    // reference points staged in smem per step

__device__ __forceinline__ uint64_t cd_pack2(float lo, float hi) {
    uint64_t r;
    asm("mov.b64 %0, {%1, %2};" : "=l"(r)
        : "r"(__float_as_uint(lo)), "r"(__float_as_uint(hi)));
    return r;
}

// d2 = qx*px + (qy*py + (qz*pz + w))  over 2 packed lanes; returns halves.
__device__ __forceinline__ void cd_dot2(uint64_t qx, uint64_t qy, uint64_t qz,
                                        uint64_t px, uint64_t py, uint64_t pz,
                                        uint64_t w,
                                        float& dlo, float& dhi) {
    uint32_t lo, hi;
    asm("{\n\t"
        ".reg .b64 t;\n\t"
        "fma.rn.f32x2 t, %2, %3, %4;\n\t"
        "fma.rn.f32x2 t, %5, %6, t;\n\t"
        "fma.rn.f32x2 t, %7, %8, t;\n\t"
        "mov.b64 {%0, %1}, t;\n\t"
        "}"
        : "=r"(lo), "=r"(hi)
        : "l"(qx), "l"(px), "l"(w),
          "l"(qy), "l"(py),
          "l"(qz), "l"(pz));
    dlo = __uint_as_float(lo);
    dhi = __uint_as_float(hi);
}

__global__ __launch_bounds__(CD_THREADS, 1)
void chamfer_min_kernel(const float* __restrict__ xyz1,
                        const float* __restrict__ xyz2,
                        float* __restrict__ out,
                        int N, int M, int B)
{
    const int dir = blockIdx.z;                 // 0: q=xyz1 vs r=xyz2 ; 1: swapped
    const int b   = blockIdx.y;

    const float* __restrict__ q = (dir == 0) ? xyz1 : xyz2;
    const float* __restrict__ r = (dir == 0) ? xyz2 : xyz1;
    const int Nq = (dir == 0) ? N : M;
    const int Nr = (dir == 0) ? M : N;
    float* __restrict__ o = out + ((dir == 0) ? 0 : (size_t)B * N);

    const float* __restrict__ qb = q + (size_t)b * Nq * 3;
    const float* __restrict__ rb = r + (size_t)b * Nr * 3;

    const int tid = threadIdx.x;

    // Per-thread query state: 2 packs of 2 points, coords pre-scaled by -2.
    float sq1[CD_P], m[CD_P];
    int   row[CD_P];
    uint64_t qxp[CD_P / 2], qyp[CD_P / 2], qzp[CD_P / 2];
    {
        float qx[CD_P], qy[CD_P], qz[CD_P];
        #pragma unroll
        for (int p = 0; p < CD_P; p++) {
            int rw = blockIdx.x * (CD_THREADS * CD_P) + p * CD_THREADS + tid;
            row[p] = rw;
            int rr = (rw < Nq) ? rw : 0;
            float x = qb[(size_t)rr * 3 + 0];
            float y = qb[(size_t)rr * 3 + 1];
            float z = qb[(size_t)rr * 3 + 2];
            sq1[p] = fmaf(x, x, fmaf(y, y, z * z));
            qx[p] = -2.0f * x; qy[p] = -2.0f * y; qz[p] = -2.0f * z;
            m[p] = 3.402823466e+38f;
        }
        #pragma unroll
        for (int p = 0; p < CD_P / 2; p++) {
            qxp[p] = cd_pack2(qx[2 * p], qx[2 * p + 1]);
            qyp[p] = cd_pack2(qy[2 * p], qy[2 * p + 1]);
            qzp[p] = cd_pack2(qz[2 * p], qz[2 * p + 1]);
        }
    }

    // Duplicated tile: A[j] = {x,x,y,y}, Bt[j] = {z,z,s,s}  (s = ||r_j||^2)
    __shared__ float4 sA[CD_TILE];
    __shared__ float4 sB[CD_TILE];

    for (int base = 0; base < Nr; base += CD_TILE) {
        {
            int j = base + tid;
            float x = 0.f, y = 0.f, z = 0.f, s = 3.402823466e+38f;
            if (j < Nr) {
                x = rb[(size_t)j * 3 + 0];
                y = rb[(size_t)j * 3 + 1];
                z = rb[(size_t)j * 3 + 2];
                s = fmaf(x, x, fmaf(y, y, z * z));
            }
            sA[tid] = make_float4(x, x, y, y);
            sB[tid] = make_float4(z, z, s, s);
        }
        __syncthreads();

        const ulonglong2* __restrict__ pA = (const ulonglong2*)sA;
        const ulonglong2* __restrict__ pB = (const ulonglong2*)sB;

        #pragma unroll 8
        for (int jj = 0; jj < CD_TILE; jj++) {
            ulonglong2 A  = pA[jj];   // A.x = {x,x}, A.y = {y,y}
            ulonglong2 Bv = pB[jj];   // Bv.x = {z,z}, Bv.y = {s,s}
            #pragma unroll
            for (int p = 0; p < CD_P / 2; p++) {
                float dlo, dhi;
                cd_dot2(qxp[p], qyp[p], qzp[p], A.x, A.y, Bv.x, Bv.y, dlo, dhi);
                m[2 * p]     = fminf(m[2 * p],     dlo);
                m[2 * p + 1] = fminf(m[2 * p + 1], dhi);
            }
        }
        __syncthreads();
    }

    #pragma unroll
    for (int p = 0; p < CD_P; p++) {
        if (row[p] < Nq) {
            float d = m[p] + sq1[p];
            o[(size_t)b * Nq + row[p]] = fmaxf(d, 0.0f);
        }
    }
}

extern "C" void kernel_launch(void* const* d_in, const int* in_sizes, int n_in,
                              void* d_out, int out_size)
{
    const float* xyz1 = (const float*)d_in[0];
    const float* xyz2 = (const float*)d_in[1];
    float* out = (float*)d_out;

    const int B = 8;
    const int N = (in_sizes[0] / 3) / B;   // 8192
    const int M = (in_sizes[1] / 3) / B;   // 8192

    int rows_per_block = CD_THREADS * CD_P;              // 1024
    int gx = (N + rows_per_block - 1) / rows_per_block;  // 8

    dim3 grid(gx, B, 2);
    dim3 block(CD_THREADS);
    chamfer_min_kernel<<<grid, block>>>(xyz1, xyz2, out, N, M, B);
}

// round 3
// speedup vs baseline: 1.2030x; 1.2030x over previous
#include <cuda_runtime.h>
#include <cstdint>

// ChamferDistance on GB300 — packed f32x2 FFMA inner loop + reference-split
// blocks combined via uint atomicMin (valid for clamped non-negative floats).
// Inputs: xyz1 [B,N,3] f32, xyz2 [B,M,3] f32, B=8, N=M=8192.
// Output: dist1 [B*N] then dist2 [B*M].

#define CD_THREADS 256
#define CD_P       4      // query points per thread (2 f32x2 packs)
#define CD_TILE    256    // reference points staged in smem per step
#define CD_SPLIT   2      // reference-dimension split (blocks per output row set)

__device__ __forceinline__ uint64_t cd_pack2(float lo, float hi) {
    uint64_t r;
    asm("mov.b64 %0, {%1, %2};" : "=l"(r)
        : "r"(__float_as_uint(lo)), "r"(__float_as_uint(hi)));
    return r;
}

// d2 = qx*px + (qy*py + (qz*pz + w)) over 2 packed lanes; returns halves.
__device__ __forceinline__ void cd_dot2(uint64_t qx, uint64_t qy, uint64_t qz,
                                        uint64_t px, uint64_t py, uint64_t pz,
                                        uint64_t w,
                                        float& dlo, float& dhi) {
    uint32_t lo, hi;
    asm("{\n\t"
        ".reg .b64 t;\n\t"
        "fma.rn.f32x2 t, %2, %3, %4;\n\t"
        "fma.rn.f32x2 t, %5, %6, t;\n\t"
        "fma.rn.f32x2 t, %7, %8, t;\n\t"
        "mov.b64 {%0, %1}, t;\n\t"
        "}"
        : "=r"(lo), "=r"(hi)
        : "l"(qx), "l"(px), "l"(w),
          "l"(qy), "l"(py),
          "l"(qz), "l"(pz));
    dlo = __uint_as_float(lo);
    dhi = __uint_as_float(hi);
}

__global__ void cd_init_out(unsigned* __restrict__ out, int n) {
    int i = blockIdx.x * blockDim.x + threadIdx.x;
    if (i < n) out[i] = 0x7F800000u;   // +inf
}

__global__ __launch_bounds__(CD_THREADS, 2)
void chamfer_min_kernel(const float* __restrict__ xyz1,
                        const float* __restrict__ xyz2,
                        float* __restrict__ out,
                        int N, int M, int B)
{
    const int zz    = blockIdx.z;
    const int dir   = zz >> 1;            // 0: q=xyz1 vs r=xyz2 ; 1: swapped
    const int split = zz & 1;             // which half of the reference set
    const int b     = blockIdx.y;

    const float* __restrict__ q = (dir == 0) ? xyz1 : xyz2;
    const float* __restrict__ r = (dir == 0) ? xyz2 : xyz1;
    const int Nq = (dir == 0) ? N : M;
    const int Nr = (dir == 0) ? M : N;
    float* __restrict__ o = out + ((dir == 0) ? 0 : (size_t)B * N);

    const float* __restrict__ qb = q + (size_t)b * Nq * 3;
    const float* __restrict__ rb = r + (size_t)b * Nr * 3;

    // This block scans reference range [r0, r1)
    const int half = (Nr + CD_SPLIT - 1) / CD_SPLIT;
    const int r0 = split * half;
    const int r1 = (r0 + half < Nr) ? (r0 + half) : Nr;

    const int tid = threadIdx.x;

    // Per-thread query state: 2 packs of 2 points, coords pre-scaled by -2.
    float sq1[CD_P], m[CD_P];
    int   row[CD_P];
    uint64_t qxp[CD_P / 2], qyp[CD_P / 2], qzp[CD_P / 2];
    {
        float qx[CD_P], qy[CD_P], qz[CD_P];
        #pragma unroll
        for (int p = 0; p < CD_P; p++) {
            int rw = blockIdx.x * (CD_THREADS * CD_P) + p * CD_THREADS + tid;
            row[p] = rw;
            int rr = (rw < Nq) ? rw : 0;
            float x = qb[(size_t)rr * 3 + 0];
            float y = qb[(size_t)rr * 3 + 1];
            float z = qb[(size_t)rr * 3 + 2];
            sq1[p] = fmaf(x, x, fmaf(y, y, z * z));
            qx[p] = -2.0f * x; qy[p] = -2.0f * y; qz[p] = -2.0f * z;
            m[p] = 3.402823466e+38f;
        }
        #pragma unroll
        for (int p = 0; p < CD_P / 2; p++) {
            qxp[p] = cd_pack2(qx[2 * p], qx[2 * p + 1]);
            qyp[p] = cd_pack2(qy[2 * p], qy[2 * p + 1]);
            qzp[p] = cd_pack2(qz[2 * p], qz[2 * p + 1]);
        }
    }

    // Duplicated tile: sA[j] = {x,x,y,y}, sB[j] = {z,z,s,s}  (s = ||r_j||^2)
    __shared__ float4 sA[CD_TILE];
    __shared__ float4 sB[CD_TILE];

    for (int base = r0; base < r1; base += CD_TILE) {
        {
            int j = base + tid;
            float x = 0.f, y = 0.f, z = 0.f, s = 3.402823466e+38f;
            if (j < r1) {
                x = rb[(size_t)j * 3 + 0];
                y = rb[(size_t)j * 3 + 1];
                z = rb[(size_t)j * 3 + 2];
                s = fmaf(x, x, fmaf(y, y, z * z));
            }
            sA[tid] = make_float4(x, x, y, y);
            sB[tid] = make_float4(z, z, s, s);
        }
        __syncthreads();

        const ulonglong2* __restrict__ pA = (const ulonglong2*)sA;
        const ulonglong2* __restrict__ pB = (const ulonglong2*)sB;

        #pragma unroll 8
        for (int jj = 0; jj < CD_TILE; jj++) {
            ulonglong2 A  = pA[jj];   // A.x = {x,x}, A.y = {y,y}
            ulonglong2 Bv = pB[jj];   // Bv.x = {z,z}, Bv.y = {s,s}
            #pragma unroll
            for (int p = 0; p < CD_P / 2; p++) {
                float dlo, dhi;
                cd_dot2(qxp[p], qyp[p], qzp[p], A.x, A.y, Bv.x, Bv.y, dlo, dhi);
                m[2 * p]     = fminf(m[2 * p],     dlo);
                m[2 * p + 1] = fminf(m[2 * p + 1], dhi);
            }
        }
        __syncthreads();
    }

    #pragma unroll
    for (int p = 0; p < CD_P; p++) {
        if (row[p] < Nq) {
            float d = fmaxf(m[p] + sq1[p], 0.0f);   // non-negative -> uint order ok
            atomicMin((unsigned*)&o[(size_t)b * Nq + row[p]], __float_as_uint(d));
        }
    }
}

extern "C" void kernel_launch(void* const* d_in, const int* in_sizes, int n_in,
                              void* d_out, int out_size)
{
    const float* xyz1 = (const float*)d_in[0];
    const float* xyz2 = (const float*)d_in[1];
    float* out = (float*)d_out;

    const int B = 8;
    const int N = (in_sizes[0] / 3) / B;   // 8192
    const int M = (in_sizes[1] / 3) / B;   // 8192

    // Init output to +inf (output poisoned by harness; atomicMin needs identity)
    {
        int n = out_size;
        cd_init_out<<<(n + 255) / 256, 256>>>((unsigned*)out, n);
    }

    int rows_per_block = CD_THREADS * CD_P;              // 1024
    int gx = (N + rows_per_block - 1) / rows_per_block;  // 8

    dim3 grid(gx, B, 2 * CD_SPLIT);                      // 8 x 8 x 4 = 256 blocks
    dim3 block(CD_THREADS);
    chamfer_min_kernel<<<grid, block>>>(xyz1, xyz2, out, N, M, B);
}

// round 4
// speedup vs baseline: 1.6450x; 1.3674x over previous
#include <cuda_runtime.h>
#include <cstdint>

// ChamferDistance on GB300 — f32x2 FFMA packed over the REFERENCE axis.
// SoA smem tile (sx/sy/sz/ss); queries pre-duplicated {q,q} and scaled by -2.
// Per jj-step a thread loads 32B smem and covers 16 (query,ref) pairs.
// Reference split across blocks, combined with uint atomicMin (non-neg floats).

#define CD_THREADS 256
#define CD_P       8      // query points per thread
#define CD_TILE    256    // reference points staged in smem per step
#define CD_SPLIT   4      // reference-dimension split

__device__ __forceinline__ uint64_t cd_dup2(float v) {
    uint64_t r;
    asm("mov.b64 %0, {%1, %1};" : "=l"(r) : "r"(__float_as_uint(v)));
    return r;
}

// {dlo,dhi} = qx*px + (qy*py + (qz*pz + s)) lane-wise over 2 ref points.
__device__ __forceinline__ void cd_dot2(uint64_t qx, uint64_t qy, uint64_t qz,
                                        uint64_t px, uint64_t py, uint64_t pz,
                                        uint64_t s,
                                        float& dlo, float& dhi) {
    uint32_t lo, hi;
    asm("{\n\t"
        ".reg .b64 t;\n\t"
        "fma.rn.f32x2 t, %2, %3, %4;\n\t"
        "fma.rn.f32x2 t, %5, %6, t;\n\t"
        "fma.rn.f32x2 t, %7, %8, t;\n\t"
        "mov.b64 {%0, %1}, t;\n\t"
        "}"
        : "=r"(lo), "=r"(hi)
        : "l"(qz), "l"(pz), "l"(s),
          "l"(qy), "l"(py),
          "l"(qx), "l"(px));
    dlo = __uint_as_float(lo);
    dhi = __uint_as_float(hi);
}

__global__ void cd_init_out(unsigned* __restrict__ out, int n) {
    int i = blockIdx.x * blockDim.x + threadIdx.x;
    if (i < n) out[i] = 0x7F800000u;   // +inf
}

__global__ __launch_bounds__(CD_THREADS, 2)
void chamfer_min_kernel(const float* __restrict__ xyz1,
                        const float* __restrict__ xyz2,
                        float* __restrict__ out,
                        int N, int M, int B)
{
    const int zz    = blockIdx.z;
    const int dir   = zz / CD_SPLIT;      // 0: q=xyz1 vs r=xyz2 ; 1: swapped
    const int split = zz % CD_SPLIT;
    const int b     = blockIdx.y;

    const float* __restrict__ q = (dir == 0) ? xyz1 : xyz2;
    const float* __restrict__ r = (dir == 0) ? xyz2 : xyz1;
    const int Nq = (dir == 0) ? N : M;
    const int Nr = (dir == 0) ? M : N;
    float* __restrict__ o = out + ((dir == 0) ? 0 : (size_t)B * N);

    const float* __restrict__ qb = q + (size_t)b * Nq * 3;
    const float* __restrict__ rb = r + (size_t)b * Nr * 3;

    const int chunk = (Nr + CD_SPLIT - 1) / CD_SPLIT;
    const int r0 = split * chunk;
    const int r1 = (r0 + chunk < Nr) ? (r0 + chunk) : Nr;

    const int tid = threadIdx.x;
    const int row0 = blockIdx.x * (CD_THREADS * CD_P);

    // Loop-invariant duplicated query packs, coords pre-scaled by -2.
    uint64_t qxd[CD_P], qyd[CD_P], qzd[CD_P];
    float sq1[CD_P], m[CD_P];
    #pragma unroll
    for (int p = 0; p < CD_P; p++) {
        int rw = row0 + p * CD_THREADS + tid;
        int rr = (rw < Nq) ? rw : 0;
        float x = qb[(size_t)rr * 3 + 0];
        float y = qb[(size_t)rr * 3 + 1];
        float z = qb[(size_t)rr * 3 + 2];
        sq1[p] = fmaf(x, x, fmaf(y, y, z * z));
        qxd[p] = cd_dup2(-2.0f * x);
        qyd[p] = cd_dup2(-2.0f * y);
        qzd[p] = cd_dup2(-2.0f * z);
        m[p] = 3.402823466e+38f;
    }

    // SoA tile: consecutive j adjacent -> ulonglong loads give {v_j, v_j+1}.
    __shared__ float sx[CD_TILE];
    __shared__ float sy[CD_TILE];
    __shared__ float sz[CD_TILE];
    __shared__ float ss[CD_TILE];

    for (int base = r0; base < r1; base += CD_TILE) {
        {
            int j = base + tid;
            float x = 0.f, y = 0.f, z = 0.f, s = 3.402823466e+38f;
            if (j < r1) {
                x = rb[(size_t)j * 3 + 0];
                y = rb[(size_t)j * 3 + 1];
                z = rb[(size_t)j * 3 + 2];
                s = fmaf(x, x, fmaf(y, y, z * z));
            }
            sx[tid] = x; sy[tid] = y; sz[tid] = z; ss[tid] = s;
        }
        __syncthreads();

        const uint64_t* __restrict__ px2 = (const uint64_t*)sx;
        const uint64_t* __restrict__ py2 = (const uint64_t*)sy;
        const uint64_t* __restrict__ pz2 = (const uint64_t*)sz;
        const uint64_t* __restrict__ ps2 = (const uint64_t*)ss;

        #pragma unroll 4
        for (int jj = 0; jj < CD_TILE / 2; jj++) {
            uint64_t px = px2[jj];   // {x_j, x_j+1} broadcast, conflict-free
            uint64_t py = py2[jj];
            uint64_t pz = pz2[jj];
            uint64_t ps = ps2[jj];
            #pragma unroll
            for (int p = 0; p < CD_P; p++) {
                float dlo, dhi;
                cd_dot2(qxd[p], qyd[p], qzd[p], px, py, pz, ps, dlo, dhi);
                m[p] = fminf(m[p], fminf(dlo, dhi));   // tree: 2 indep FMNMX
            }
        }
        __syncthreads();
    }

    #pragma unroll
    for (int p = 0; p < CD_P; p++) {
        int rw = row0 + p * CD_THREADS + tid;
        if (rw < Nq) {
            float d = fmaxf(m[p] + sq1[p], 0.0f);   // non-negative -> uint order
            atomicMin((unsigned*)&o[(size_t)b * Nq + rw], __float_as_uint(d));
        }
    }
}

extern "C" void kernel_launch(void* const* d_in, const int* in_sizes, int n_in,
                              void* d_out, int out_size)
{
    const float* xyz1 = (const float*)d_in[0];
    const float* xyz2 = (const float*)d_in[1];
    float* out = (float*)d_out;

    const int B = 8;
    const int N = (in_sizes[0] / 3) / B;   // 8192
    const int M = (in_sizes[1] / 3) / B;   // 8192

    // Output must start at +inf for atomicMin combining.
    cd_init_out<<<(out_size + 255) / 256, 256>>>((unsigned*)out, out_size);

    int rows_per_block = CD_THREADS * CD_P;              // 2048
    int gx = (N + rows_per_block - 1) / rows_per_block;  // 4

    dim3 grid(gx, B, 2 * CD_SPLIT);                      // 4 x 8 x 8 = 256 blocks
    dim3 block(CD_THREADS);
    chamfer_min_kernel<<<grid, block>>>(xyz1, xyz2, out, N, M, B);
}

// round 5
// speedup vs baseline: 1.8471x; 1.1228x over previous
#include <cuda_runtime.h>
#include <cstdint>

// ChamferDistance on GB300 — f32x2 FFMA packed over the REFERENCE axis.
// Round 5: occupancy 3 CTAs/SM (P=4, <=85 regs) + 8-way ref split (1024 CTAs)
// for load balancing. Partial minima combined via uint atomicMin.

#define CD_THREADS 256
#define CD_P       4      // query points per thread
#define CD_TILE    256    // reference points staged in smem per step
#define CD_SPLIT   8      // reference-dimension split

__device__ __forceinline__ uint64_t cd_dup2(float v) {
    uint64_t r;
    asm("mov.b64 %0, {%1, %1};" : "=l"(r) : "r"(__float_as_uint(v)));
    return r;
}

// {dlo,dhi} = qx*px + (qy*py + (qz*pz + s)) lane-wise over 2 ref points.
__device__ __forceinline__ void cd_dot2(uint64_t qx, uint64_t qy, uint64_t qz,
                                        uint64_t px, uint64_t py, uint64_t pz,
                                        uint64_t s,
                                        float& dlo, float& dhi) {
    uint32_t lo, hi;
    asm("{\n\t"
        ".reg .b64 t;\n\t"
        "fma.rn.f32x2 t, %2, %3, %4;\n\t"
        "fma.rn.f32x2 t, %5, %6, t;\n\t"
        "fma.rn.f32x2 t, %7, %8, t;\n\t"
        "mov.b64 {%0, %1}, t;\n\t"
        "}"
        : "=r"(lo), "=r"(hi)
        : "l"(qz), "l"(pz), "l"(s),
          "l"(qy), "l"(py),
          "l"(qx), "l"(px));
    dlo = __uint_as_float(lo);
    dhi = __uint_as_float(hi);
}

__global__ void cd_init_out(unsigned* __restrict__ out, int n) {
    int i = blockIdx.x * blockDim.x + threadIdx.x;
    if (i < n) out[i] = 0x7F800000u;   // +inf
}

__global__ __launch_bounds__(CD_THREADS, 3)
void chamfer_min_kernel(const float* __restrict__ xyz1,
                        const float* __restrict__ xyz2,
                        float* __restrict__ out,
                        int N, int M, int B)
{
    const int zz    = blockIdx.z;
    const int dir   = zz / CD_SPLIT;      // 0: q=xyz1 vs r=xyz2 ; 1: swapped
    const int split = zz % CD_SPLIT;
    const int b     = blockIdx.y;

    const float* __restrict__ q = (dir == 0) ? xyz1 : xyz2;
    const float* __restrict__ r = (dir == 0) ? xyz2 : xyz1;
    const int Nq = (dir == 0) ? N : M;
    const int Nr = (dir == 0) ? M : N;
    float* __restrict__ o = out + ((dir == 0) ? 0 : (size_t)B * N);

    const float* __restrict__ qb = q + (size_t)b * Nq * 3;
    const float* __restrict__ rb = r + (size_t)b * Nr * 3;

    const int chunk = (Nr + CD_SPLIT - 1) / CD_SPLIT;
    const int r0 = split * chunk;
    const int r1 = (r0 + chunk < Nr) ? (r0 + chunk) : Nr;

    const int tid = threadIdx.x;
    const int row0 = blockIdx.x * (CD_THREADS * CD_P);

    // Loop-invariant duplicated query packs, coords pre-scaled by -2.
    uint64_t qxd[CD_P], qyd[CD_P], qzd[CD_P];
    float sq1[CD_P], m[CD_P];
    #pragma unroll
    for (int p = 0; p < CD_P; p++) {
        int rw = row0 + p * CD_THREADS + tid;
        int rr = (rw < Nq) ? rw : 0;
        float x = qb[(size_t)rr * 3 + 0];
        float y = qb[(size_t)rr * 3 + 1];
        float z = qb[(size_t)rr * 3 + 2];
        sq1[p] = fmaf(x, x, fmaf(y, y, z * z));
        qxd[p] = cd_dup2(-2.0f * x);
        qyd[p] = cd_dup2(-2.0f * y);
        qzd[p] = cd_dup2(-2.0f * z);
        m[p] = 3.402823466e+38f;
    }

    // SoA tile: consecutive j adjacent -> u64 loads give {v_j, v_j+1}.
    __shared__ float sx[CD_TILE];
    __shared__ float sy[CD_TILE];
    __shared__ float sz[CD_TILE];
    __shared__ float ss[CD_TILE];

    for (int base = r0; base < r1; base += CD_TILE) {
        {
            int j = base + tid;
            float x = 0.f, y = 0.f, z = 0.f, s = 3.402823466e+38f;
            if (j < r1) {
                x = rb[(size_t)j * 3 + 0];
                y = rb[(size_t)j * 3 + 1];
                z = rb[(size_t)j * 3 + 2];
                s = fmaf(x, x, fmaf(y, y, z * z));
            }
            sx[tid] = x; sy[tid] = y; sz[tid] = z; ss[tid] = s;
        }
        __syncthreads();

        const uint64_t* __restrict__ px2 = (const uint64_t*)sx;
        const uint64_t* __restrict__ py2 = (const uint64_t*)sy;
        const uint64_t* __restrict__ pz2 = (const uint64_t*)sz;
        const uint64_t* __restrict__ ps2 = (const uint64_t*)ss;

        #pragma unroll 2
        for (int jj = 0; jj < CD_TILE / 2; jj++) {
            uint64_t px = px2[jj];   // {x_j, x_j+1} broadcast, conflict-free
            uint64_t py = py2[jj];
            uint64_t pz = pz2[jj];
            uint64_t ps = ps2[jj];
            #pragma unroll
            for (int p = 0; p < CD_P; p++) {
                float dlo, dhi;
                cd_dot2(qxd[p], qyd[p], qzd[p], px, py, pz, ps, dlo, dhi);
                m[p] = fminf(m[p], fminf(dlo, dhi));
            }
        }
        __syncthreads();
    }

    #pragma unroll
    for (int p = 0; p < CD_P; p++) {
        int rw = row0 + p * CD_THREADS + tid;
        if (rw < Nq) {
            float d = fmaxf(m[p] + sq1[p], 0.0f);   // non-negative -> uint order
            atomicMin((unsigned*)&o[(size_t)b * Nq + rw], __float_as_uint(d));
        }
    }
}

extern "C" void kernel_launch(void* const* d_in, const int* in_sizes, int n_in,
                              void* d_out, int out_size)
{
    const float* xyz1 = (const float*)d_in[0];
    const float* xyz2 = (const float*)d_in[1];
    float* out = (float*)d_out;

    const int B = 8;
    const int N = (in_sizes[0] / 3) / B;   // 8192
    const int M = (in_sizes[1] / 3) / B;   // 8192

    // Output must start at +inf for atomicMin combining.
    cd_init_out<<<(out_size + 255) / 256, 256>>>((unsigned*)out, out_size);

    int rows_per_block = CD_THREADS * CD_P;              // 1024
    int gx = (N + rows_per_block - 1) / rows_per_block;  // 8

    dim3 grid(gx, B, 2 * CD_SPLIT);                      // 8 x 8 x 16 = 1024 blocks
    dim3 block(CD_THREADS);
    chamfer_min_kernel<<<grid, block>>>(xyz1, xyz2, out, N, M, B);
}